// round 9
// baseline (speedup 1.0000x reference)
#include <cuda_runtime.h>
#include <cuda_bf16.h>
#include <cstdint>

// ---------------- problem constants ----------------
#define BB      2
#define LL      4096
#define DM      768
#define DIN     1536
#define NH      24
#define HD      64
#define DS      64
#define CONVD   1664          // DIN + 2*DS
#define DPROJ   3224          // 2*DIN + 2*DS + NH
#define BLROWS  (BB*LL)       // 8192
#define CHUNK   64
#define NCHUNK  (LL/CHUNK)    // 64
#define HG      4             // heads per scan block

// single dynamic-smem symbol for the whole TU
extern __shared__ unsigned char dynsm[];

// ---------------- scratch ----------------
__device__ float g_zx   [(size_t)BLROWS*DPROJ];
__device__ float g_xbc  [(size_t)BLROWS*CONVD];
__device__ float g_dt   [(size_t)BLROWS*NH];
__device__ float g_dA   [(size_t)BLROWS*NH];
__device__ float g_S    [(size_t)BB*NH*NCHUNK*DS*HD];
__device__ float g_hini [(size_t)BB*NH*NCHUNK*DS*HD];
__device__ float g_P    [BB*NH*NCHUNK];
__device__ float g_y    [(size_t)BLROWS*DIN];

__device__ __nv_bfloat16 g_xh [(size_t)BLROWS*DM];
__device__ __nv_bfloat16 g_xl [(size_t)BLROWS*DM];
__device__ __nv_bfloat16 g_wih[(size_t)DPROJ*DM];
__device__ __nv_bfloat16 g_wil[(size_t)DPROJ*DM];
__device__ __nv_bfloat16 g_yh [(size_t)BLROWS*DIN];
__device__ __nv_bfloat16 g_yl [(size_t)BLROWS*DIN];
__device__ __nv_bfloat16 g_woh[(size_t)DM*DIN];
__device__ __nv_bfloat16 g_wol[(size_t)DM*DIN];

// ---------------- packed f32x2 helpers ----------------
typedef unsigned long long u64t;
__device__ __forceinline__ u64t pack2(float v) {
    u64t r; asm("mov.b64 %0, {%1,%1};" : "=l"(r) : "f"(v)); return r;
}
__device__ __forceinline__ u64t fma2(u64t a, u64t b, u64t c) {
    u64t d; asm("fma.rn.f32x2 %0, %1, %2, %3;" : "=l"(d) : "l"(a), "l"(b), "l"(c)); return d;
}
__device__ __forceinline__ u64t mul2(u64t a, u64t b) {
    u64t d; asm("mul.rn.f32x2 %0, %1, %2;" : "=l"(d) : "l"(a), "l"(b)); return d;
}
__device__ __forceinline__ void unpack2(u64t v, float& lo, float& hi) {
    asm("mov.b64 {%0,%1}, %2;" : "=f"(lo), "=f"(hi) : "l"(v));
}

// ======================= split helpers =====================================
__global__ void __launch_bounds__(256) split_x_k(
    const float* __restrict__ X, __nv_bfloat16* __restrict__ Xh,
    __nv_bfloat16* __restrict__ Xl, int n4)
{
    int i = blockIdx.x * blockDim.x + threadIdx.x;
    if (i >= n4) return;
    float4 v = reinterpret_cast<const float4*>(X)[i];
    __nv_bfloat16 h0 = __float2bfloat16(v.x), h1 = __float2bfloat16(v.y);
    __nv_bfloat16 h2 = __float2bfloat16(v.z), h3 = __float2bfloat16(v.w);
    __nv_bfloat162 hh0{h0, h1}, hh1{h2, h3};
    __nv_bfloat162 ll0{__float2bfloat16(v.x - __bfloat162float(h0)),
                       __float2bfloat16(v.y - __bfloat162float(h1))};
    __nv_bfloat162 ll1{__float2bfloat16(v.z - __bfloat162float(h2)),
                       __float2bfloat16(v.w - __bfloat162float(h3))};
    reinterpret_cast<__nv_bfloat162*>(Xh)[i * 2 + 0] = hh0;
    reinterpret_cast<__nv_bfloat162*>(Xh)[i * 2 + 1] = hh1;
    reinterpret_cast<__nv_bfloat162*>(Xl)[i * 2 + 0] = ll0;
    reinterpret_cast<__nv_bfloat162*>(Xl)[i * 2 + 1] = ll1;
}

__global__ void __launch_bounds__(256) tsplit_k(
    const float* __restrict__ W, __nv_bfloat16* __restrict__ Th,
    __nv_bfloat16* __restrict__ Tl, int K, int N)
{
    __shared__ float tile[32][33];
    int k0 = blockIdx.x * 32, n0 = blockIdx.y * 32;
    int tx = threadIdx.x % 32, ty = threadIdx.x / 32;
#pragma unroll
    for (int i = ty; i < 32; i += 8) {
        int k = k0 + i, n = n0 + tx;
        tile[i][tx] = (k < K && n < N) ? W[(size_t)k * N + n] : 0.f;
    }
    __syncthreads();
#pragma unroll
    for (int i = ty; i < 32; i += 8) {
        int n = n0 + i, k = k0 + tx;
        if (n < N && k < K) {
            float v = tile[tx][i];
            __nv_bfloat16 h = __float2bfloat16(v);
            Th[(size_t)n * K + k] = h;
            Tl[(size_t)n * K + k] = __float2bfloat16(v - __bfloat162float(h));
        }
    }
}

// ======================= tensor-core split-bf16 GEMM ========================
// C[M,N](fp32) = Ah@Bh^T + Ah@Bl^T + Al@Bh^T ; A[M][K], B stored [N][K].
// Templated: BM x 128 CTA tile, NT = 2*BM threads, warp tile 64x32,
// 3-stage cp.async pipeline, 1 barrier per iter.
#define GSTRIDE 40
#define BPART   (128*GSTRIDE)          // B matrix rows (elems per half)

__device__ __forceinline__ void cp16(uint32_t s, const void* g, bool pred) {
    int sz = pred ? 16 : 0;
    asm volatile("cp.async.cg.shared.global [%0], [%1], 16, %2;\n"
                 :: "r"(s), "l"(g), "r"(sz));
}
__device__ __forceinline__ void mma_bf16(float* d, const uint32_t* a, const uint32_t* b) {
    asm volatile("mma.sync.aligned.m16n8k16.row.col.f32.bf16.bf16.f32 "
                 "{%0,%1,%2,%3}, {%4,%5,%6,%7}, {%8,%9}, {%0,%1,%2,%3};"
                 : "+f"(d[0]), "+f"(d[1]), "+f"(d[2]), "+f"(d[3])
                 : "r"(a[0]), "r"(a[1]), "r"(a[2]), "r"(a[3]), "r"(b[0]), "r"(b[1]));
}
__device__ __forceinline__ void ldsm4(uint32_t* r, uint32_t a) {
    asm volatile("ldmatrix.sync.aligned.m8n8.x4.shared.b16 {%0,%1,%2,%3}, [%4];"
                 : "=r"(r[0]), "=r"(r[1]), "=r"(r[2]), "=r"(r[3]) : "r"(a));
}

template <int BM, int NT>
__global__ void __launch_bounds__(NT) mma_gemm_k(
    const __nv_bfloat16* __restrict__ Ah, const __nv_bfloat16* __restrict__ Al,
    const __nv_bfloat16* __restrict__ Bh, const __nv_bfloat16* __restrict__ Bl,
    float* __restrict__ C, int Nn, int K)
{
    constexpr int APART = BM * GSTRIDE;                  // elems per A half
    constexpr int STAGE_BYTES = (2 * APART + 2 * BPART) * 2;
    constexpr int AROWS_PER_STEP = NT / 4;               // rows covered per load step
    constexpr int NA = BM / AROWS_PER_STEP;              // A load steps (=2)
    constexpr int NB = 128 / AROWS_PER_STEP;             // B load steps

    const int tid  = threadIdx.x;
    const int lane = tid & 31;
    const int wid  = tid >> 5;
    const int wm   = wid >> 2;           // 0..BM/64-1
    const int wn   = wid & 3;            // 0..3
    const int g    = lane >> 2;
    const int tig  = lane & 3;

    const int row0 = blockIdx.y * BM;
    const int col0 = blockIdx.x * 128;
    const int iters = K / 32;
    const int r0 = tid >> 2, s0 = tid & 3;

    // ldmatrix lane address components
    const int arow = (lane & 7) + ((lane >> 3) & 1) * 8;
    const int acol = ((lane >> 4) & 1) * 8;
    const int brow = (lane & 7) + ((lane >> 4) & 1) * 8;
    const int bcol = ((lane >> 3) & 1) * 8;

    const uint32_t smbase = (uint32_t)__cvta_generic_to_shared(dynsm);
    uint32_t aoff[4], boff[2];
#pragma unroll
    for (int mi = 0; mi < 4; mi++)
        aoff[mi] = (uint32_t)(((wm * 64 + mi * 16 + arow) * GSTRIDE + acol) * 2);
#pragma unroll
    for (int nj = 0; nj < 2; nj++)
        boff[nj] = (uint32_t)(((wn * 32 + nj * 16 + brow) * GSTRIDE + bcol) * 2);

    float acc[4][4][4];
#pragma unroll
    for (int mi = 0; mi < 4; mi++)
#pragma unroll
        for (int ni = 0; ni < 4; ni++)
#pragma unroll
            for (int q = 0; q < 4; q++) acc[mi][ni][q] = 0.f;

    auto load_tiles = [&](int buf, int it) {
        const int k0 = it * 32;
        uint32_t b = smbase + buf * STAGE_BYTES;
#pragma unroll
        for (int j = 0; j < NA; j++) {
            int r = r0 + j * AROWS_PER_STEP;
            uint32_t soff = (uint32_t)(r * GSTRIDE + s0 * 8) * 2;
            size_t ga = (size_t)(row0 + r) * K + k0 + s0 * 8;
            cp16(b + soff, Ah + ga, true);
            cp16(b + APART * 2 + soff, Al + ga, true);
        }
#pragma unroll
        for (int j = 0; j < NB; j++) {
            int r = (r0 + j * AROWS_PER_STEP) & 127;
            if (NB > 0 && (NB == 2 || r0 < 128)) {
                uint32_t soff = (uint32_t)(r * GSTRIDE + s0 * 8) * 2;
                int nb = col0 + r;
                bool p = nb < Nn;
                size_t gb = (size_t)(p ? nb : 0) * K + k0 + s0 * 8;
                cp16(b + 2 * APART * 2 + soff, Bh + gb, p);
                cp16(b + 2 * APART * 2 + BPART * 2 + soff, Bl + gb, p);
            }
        }
        asm volatile("cp.async.commit_group;\n" ::);
    };

    // prologue: fill 2 of 3 stages
    load_tiles(0, 0);
    load_tiles(1, 1);

    for (int it = 0; it < iters; it++) {
        asm volatile("cp.async.wait_group 1;\n" ::);
        __syncthreads();

        const int buf = it % 3;
        uint32_t bA  = smbase + buf * STAGE_BYTES;
        uint32_t bAl = bA + APART * 2;
        uint32_t bBh = bA + 2 * APART * 2;
        uint32_t bBl = bBh + BPART * 2;

#pragma unroll
        for (int kk = 0; kk < 2; kk++) {
            const uint32_t kof = kk * 32;   // 16 bf16 = 32 bytes
            uint32_t ah[4][4], al[4][4], bh[2][4], bl[2][4];
#pragma unroll
            for (int mi = 0; mi < 4; mi++) ldsm4(ah[mi], bA + aoff[mi] + kof);
#pragma unroll
            for (int mi = 0; mi < 4; mi++) ldsm4(al[mi], bAl + aoff[mi] + kof);
#pragma unroll
            for (int nj = 0; nj < 2; nj++) ldsm4(bh[nj], bBh + boff[nj] + kof);
#pragma unroll
            for (int nj = 0; nj < 2; nj++) ldsm4(bl[nj], bBl + boff[nj] + kof);

#pragma unroll
            for (int mi = 0; mi < 4; mi++)
#pragma unroll
                for (int ni = 0; ni < 4; ni++)
                    mma_bf16(acc[mi][ni], ah[mi], &bh[ni >> 1][(ni & 1) * 2]);
#pragma unroll
            for (int mi = 0; mi < 4; mi++)
#pragma unroll
                for (int ni = 0; ni < 4; ni++)
                    mma_bf16(acc[mi][ni], ah[mi], &bl[ni >> 1][(ni & 1) * 2]);
#pragma unroll
            for (int mi = 0; mi < 4; mi++)
#pragma unroll
                for (int ni = 0; ni < 4; ni++)
                    mma_bf16(acc[mi][ni], al[mi], &bh[ni >> 1][(ni & 1) * 2]);
        }

        const int nx = it + 2;
        if (nx < iters) {
            load_tiles(nx % 3, nx);
        } else {
            asm volatile("cp.async.commit_group;\n" ::);   // keep group count uniform
        }
    }

#pragma unroll
    for (int mi = 0; mi < 4; mi++) {
        int ra = row0 + wm * 64 + mi * 16 + g;
#pragma unroll
        for (int ni = 0; ni < 4; ni++) {
            int c = col0 + wn * 32 + ni * 8 + 2 * tig;
            if (c < Nn) {
                *reinterpret_cast<float2*>(&C[(size_t)ra * Nn + c]) =
                    make_float2(acc[mi][ni][0], acc[mi][ni][1]);
                *reinterpret_cast<float2*>(&C[(size_t)(ra + 8) * Nn + c]) =
                    make_float2(acc[mi][ni][2], acc[mi][ni][3]);
            }
        }
    }
}

#define SMEM_BM256 (3 * (2 * 256 * GSTRIDE + 2 * 128 * GSTRIDE) * 2)   // 184320
#define SMEM_BM128 (3 * (2 * 128 * GSTRIDE + 2 * 128 * GSTRIDE) * 2)   // 122880

// ---------------- conv: smem-tiled depthwise causal conv + silu -------------
__global__ void __launch_bounds__(256) conv_k(
    const float* __restrict__ conv_w, const float* __restrict__ conv_b)
{
    __shared__ float st[35][128];
    const int c0 = blockIdx.x * 128;
    const int b  = blockIdx.y >> 7;           // /128
    const int lg = blockIdx.y & 127;
    const int l0 = lg * 32;

    for (int i = threadIdx.x; i < 35 * 128; i += 256) {
        int r = i >> 7, cc = i & 127;
        int ls = l0 - 3 + r;
        st[r][cc] = (ls >= 0) ? g_zx[(size_t)(b * LL + ls) * DPROJ + DIN + c0 + cc] : 0.f;
    }
    __syncthreads();

    for (int i = threadIdx.x; i < 32 * 128; i += 256) {
        int r = i >> 7, cc = i & 127;
        int c = c0 + cc;
        float w0 = conv_w[c * 4 + 0], w1 = conv_w[c * 4 + 1];
        float w2 = conv_w[c * 4 + 2], w3 = conv_w[c * 4 + 3];
        float acc = conv_b[c];
        acc = fmaf(st[r + 0][cc], w0, acc);
        acc = fmaf(st[r + 1][cc], w1, acc);
        acc = fmaf(st[r + 2][cc], w2, acc);
        acc = fmaf(st[r + 3][cc], w3, acc);
        g_xbc[(size_t)(b * LL + l0 + r) * CONVD + c] = acc / (1.f + __expf(-acc));
    }
}

// ---------------- dt prep ----------------------------------------------------
__global__ void __launch_bounds__(256) dt_k(
    const float* __restrict__ dt_bias, const float* __restrict__ A_log)
{
    int i = blockIdx.x * blockDim.x + threadIdx.x;
    if (i >= BLROWS * NH) return;
    int row = i / NH, h = i % NH;
    float v = g_zx[(size_t)row * DPROJ + (DIN + CONVD) + h] + dt_bias[h];
    float sp = (v > 20.f) ? v : log1pf(expf(v));
    float Ah = -expf(A_log[h]);
    g_dt[i] = sp;
    g_dA[i] = expf(sp * Ah);
}

// ---------------- scan smem layout (floats) ----------------------------------
#define SC_B   0
#define SC_C   4096
#define SC_DA  8192
#define SC_DT  8448
#define SC_X   8704
#define SCAN_SMEM_FLOATS (8704 + HG*64*64)
#define SCAN_SMEM_BYTES  (SCAN_SMEM_FLOATS*4)    // 100352

__device__ __forceinline__ void scan_stage(float* sm, int b, int c, int hg, bool withC)
{
    const int tid = threadIdx.x;
    const int rowbase = b * LL + c * CHUNK;
    for (int i = tid; i < 64 * 16; i += 256) {
        int t = i >> 4, q = i & 15;
        const float* xr = g_xbc + (size_t)(rowbase + t) * CONVD;
        *reinterpret_cast<float4*>(sm + SC_B + t * 64 + q * 4) =
            *reinterpret_cast<const float4*>(xr + DIN + q * 4);
        if (withC)
            *reinterpret_cast<float4*>(sm + SC_C + t * 64 + q * 4) =
                *reinterpret_cast<const float4*>(xr + DIN + DS + q * 4);
    }
    for (int i = tid; i < HG * 64; i += 256) {
        int hl = i >> 6, t = i & 63;
        int row = rowbase + t;
        sm[SC_DA + i] = g_dA[(size_t)row * NH + hg * HG + hl];
        sm[SC_DT + i] = g_dt[(size_t)row * NH + hg * HG + hl];
    }
    for (int i = tid; i < HG * 64 * 16; i += 256) {
        int hl = i >> 10, rem = i & 1023, t = rem >> 4, q = rem & 15;
        const float* xr = g_xbc + (size_t)(rowbase + t) * CONVD;
        *reinterpret_cast<float4*>(sm + SC_X + hl * 4096 + t * 64 + q * 4) =
            *reinterpret_cast<const float4*>(xr + (hg * HG + hl) * HD + q * 4);
    }
}

// ---------------- scan pass 1 -----------------------------------------------
__global__ void __launch_bounds__(256) scan1_k()
{
    float* sm = reinterpret_cast<float*>(dynsm);
    const int bx = blockIdx.x;
    const int c  = bx % NCHUNK;
    const int r2 = bx / NCHUNK;
    const int b  = r2 / (NH / HG);
    const int hg = r2 % (NH / HG);

    scan_stage(sm, b, c, hg, false);
    __syncthreads();

    const int wid  = threadIdx.x >> 5;
    const int lane = threadIdx.x & 31;
    const int hl   = wid >> 1;
    const int pg   = wid & 1;
    const int p    = pg * 32 + lane;
    const int h    = hg * HG + hl;

    u64t st[32];
#pragma unroll
    for (int n = 0; n < 32; n++) st[n] = 0ull;
    float Pp = 1.f;

    const float* sxp = sm + SC_X + hl * 4096 + p;
    const float* sdA = sm + SC_DA + hl * 64;
    const float* sdt = sm + SC_DT + hl * 64;

    for (int t = 0; t < CHUNK; t++) {
        float dAv = sdA[t];
        float u = sdt[t] * sxp[t * 64];
        Pp *= dAv;
        u64t dA2 = pack2(dAv), u2 = pack2(u);
        const ulonglong2* B2 = reinterpret_cast<const ulonglong2*>(sm + SC_B + t * 64);
#pragma unroll
        for (int n4 = 0; n4 < 16; n4++) {
            ulonglong2 bb = B2[n4];
            st[2 * n4 + 0] = fma2(dA2, st[2 * n4 + 0], mul2(u2, bb.x));
            st[2 * n4 + 1] = fma2(dA2, st[2 * n4 + 1], mul2(u2, bb.y));
        }
    }

    const int bhc = (b * NH + h) * NCHUNK + c;
    float* Sp = g_S + (size_t)bhc * DS * HD;
#pragma unroll
    for (int n2 = 0; n2 < 32; n2++) {
        float lo, hi; unpack2(st[n2], lo, hi);
        Sp[(2 * n2 + 0) * HD + p] = lo;
        Sp[(2 * n2 + 1) * HD + p] = hi;
    }
    if (pg == 0 && lane == 0) g_P[bhc] = Pp;
}

// ---------------- combine ----------------------------------------------------
__global__ void __launch_bounds__(256) combine_k()
{
    const int i = blockIdx.x * blockDim.x + threadIdx.x;
    if (i >= BB * NH * DS * HD) return;
    const int pn = i % (DS * HD);
    const int bh = i / (DS * HD);
    float hp = 0.f;
    const float* P = g_P + bh * NCHUNK;
    const size_t base = (size_t)bh * NCHUNK * DS * HD + pn;
    for (int c = 0; c < NCHUNK; c++) {
        g_hini[base + (size_t)c * DS * HD] = hp;
        hp = fmaf(hp, P[c], g_S[base + (size_t)c * DS * HD]);
    }
}

// ---------------- scan pass 2 -----------------------------------------------
__global__ void __launch_bounds__(256) scan2_k(const float* __restrict__ Dp)
{
    float* sm = reinterpret_cast<float*>(dynsm);
    const int bx = blockIdx.x;
    const int c  = bx % NCHUNK;
    const int r2 = bx / NCHUNK;
    const int b  = r2 / (NH / HG);
    const int hg = r2 % (NH / HG);

    scan_stage(sm, b, c, hg, true);
    __syncthreads();

    const int wid  = threadIdx.x >> 5;
    const int lane = threadIdx.x & 31;
    const int hl   = wid >> 1;
    const int pg   = wid & 1;
    const int p    = pg * 32 + lane;
    const int h    = hg * HG + hl;
    const int bhc  = (b * NH + h) * NCHUNK + c;

    u64t st[32];
    const float* hiv = g_hini + (size_t)bhc * DS * HD;
#pragma unroll
    for (int n2 = 0; n2 < 32; n2++) {
        float lo = hiv[(2 * n2 + 0) * HD + p];
        float hi = hiv[(2 * n2 + 1) * HD + p];
        u64t v; asm("mov.b64 %0, {%1,%2};" : "=l"(v) : "f"(lo), "f"(hi));
        st[n2] = v;
    }

    const float Dh = Dp[h];
    const float* sxp = sm + SC_X + hl * 4096 + p;
    const float* sdA = sm + SC_DA + hl * 64;
    const float* sdt = sm + SC_DT + hl * 64;
    const int rowbase = b * LL + c * CHUNK;

    for (int t = 0; t < CHUNK; t++) {
        float dAv = sdA[t];
        float x = sxp[t * 64];
        float u = sdt[t] * x;
        u64t dA2 = pack2(dAv), u2 = pack2(u);
        u64t y2 = 0ull;
        const ulonglong2* B2 = reinterpret_cast<const ulonglong2*>(sm + SC_B + t * 64);
        const ulonglong2* C2 = reinterpret_cast<const ulonglong2*>(sm + SC_C + t * 64);
#pragma unroll
        for (int n4 = 0; n4 < 16; n4++) {
            ulonglong2 bb = B2[n4];
            ulonglong2 cc = C2[n4];
            st[2 * n4 + 0] = fma2(dA2, st[2 * n4 + 0], mul2(u2, bb.x));
            st[2 * n4 + 1] = fma2(dA2, st[2 * n4 + 1], mul2(u2, bb.y));
            y2 = fma2(st[2 * n4 + 0], cc.x, y2);
            y2 = fma2(st[2 * n4 + 1], cc.y, y2);
        }
        float ylo, yhi; unpack2(y2, ylo, yhi);
        g_y[(size_t)(rowbase + t) * DIN + h * HD + p] = fmaf(Dh, x, ylo + yhi);
    }
}

// ---------------- gate + RMSNorm + split to bf16 ----------------------------
__global__ void __launch_bounds__(512) gatenorm_k(const float* __restrict__ norm_w)
{
    const int row = blockIdx.x;
    const float* zrow = g_zx + (size_t)row * DPROJ;
    const float* yrow = g_y + (size_t)row * DIN;

    float gv[3];
    float ss = 0.f;
#pragma unroll
    for (int j = 0; j < 3; j++) {
        int i = threadIdx.x + j * 512;
        float z = zrow[i];
        float gg = yrow[i] * (z / (1.f + __expf(-z)));
        gv[j] = gg;
        ss = fmaf(gg, gg, ss);
    }

    __shared__ float red[16];
#pragma unroll
    for (int o = 16; o; o >>= 1) ss += __shfl_xor_sync(0xffffffffu, ss, o);
    if ((threadIdx.x & 31) == 0) red[threadIdx.x >> 5] = ss;
    __syncthreads();
    if (threadIdx.x < 16) {
        float v = red[threadIdx.x];
#pragma unroll
        for (int o = 8; o; o >>= 1) v += __shfl_xor_sync(0x0000ffffu, v, o);
        if (threadIdx.x == 0) red[0] = v;
    }
    __syncthreads();
    const float scale = rsqrtf(red[0] / (float)DIN + 1e-5f);
#pragma unroll
    for (int j = 0; j < 3; j++) {
        int i = threadIdx.x + j * 512;
        float v = gv[j] * scale * norm_w[i];
        __nv_bfloat16 h = __float2bfloat16(v);
        g_yh[(size_t)row * DIN + i] = h;
        g_yl[(size_t)row * DIN + i] = __float2bfloat16(v - __bfloat162float(h));
    }
}

// ---------------- launch ----------------------------------------------------
extern "C" void kernel_launch(void* const* d_in, const int* in_sizes, int n_in,
                              void* d_out, int out_size)
{
    const float* x       = (const float*)d_in[0];
    const float* W_in    = (const float*)d_in[1];
    const float* conv_w  = (const float*)d_in[2];
    const float* conv_b  = (const float*)d_in[3];
    const float* dt_bias = (const float*)d_in[4];
    const float* A_log   = (const float*)d_in[5];
    const float* Dp      = (const float*)d_in[6];
    const float* norm_w  = (const float*)d_in[7];
    const float* W_out   = (const float*)d_in[8];
    float* out           = (float*)d_out;

    float* zx = nullptr;
    __nv_bfloat16 *xh, *xl, *wih, *wil, *yh, *yl, *woh, *wol;
    cudaGetSymbolAddress((void**)&zx,  g_zx);
    cudaGetSymbolAddress((void**)&xh,  g_xh);
    cudaGetSymbolAddress((void**)&xl,  g_xl);
    cudaGetSymbolAddress((void**)&wih, g_wih);
    cudaGetSymbolAddress((void**)&wil, g_wil);
    cudaGetSymbolAddress((void**)&yh,  g_yh);
    cudaGetSymbolAddress((void**)&yl,  g_yl);
    cudaGetSymbolAddress((void**)&woh, g_woh);
    cudaGetSymbolAddress((void**)&wol, g_wol);

    static bool attr_set = false;
    if (!attr_set) {
        cudaFuncSetAttribute(mma_gemm_k<256, 512>,
                             cudaFuncAttributeMaxDynamicSharedMemorySize, SMEM_BM256);
        cudaFuncSetAttribute(mma_gemm_k<128, 256>,
                             cudaFuncAttributeMaxDynamicSharedMemorySize, SMEM_BM128);
        cudaFuncSetAttribute(scan1_k, cudaFuncAttributeMaxDynamicSharedMemorySize,
                             SCAN_SMEM_BYTES);
        cudaFuncSetAttribute(scan2_k, cudaFuncAttributeMaxDynamicSharedMemorySize,
                             SCAN_SMEM_BYTES);
        attr_set = true;
    }

    // 0) split inputs
    {
        int n4 = BLROWS * DM / 4;
        split_x_k<<<(n4 + 255) / 256, 256>>>(x, xh, xl, n4);
        tsplit_k<<<dim3(DM / 32, (DPROJ + 31) / 32), 256>>>(W_in, wih, wil, DM, DPROJ);
        tsplit_k<<<dim3(DIN / 32, DM / 32), 256>>>(W_out, woh, wol, DIN, DM);
    }

    // 1) zxbcdt = x @ W_in   (256x128 tile, 16 warps)
    mma_gemm_k<256, 512><<<dim3((DPROJ + 127) / 128, BLROWS / 256), 512, SMEM_BM256>>>(
        xh, xl, wih, wil, zx, DPROJ, DM);

    // 2) conv + silu ; dt prep
    conv_k<<<dim3(CONVD / 128, BB * (LL / 32)), 256>>>(conv_w, conv_b);
    dt_k<<<(BLROWS * NH + 255) / 256, 256>>>(dt_bias, A_log);

    // 3) chunked scan
    {
        int blocks = BB * (NH / HG) * NCHUNK;   // 768
        scan1_k<<<blocks, 256, SCAN_SMEM_BYTES>>>();
        int nstates = BB * NH * DS * HD;
        combine_k<<<(nstates + 255) / 256, 256>>>();
        scan2_k<<<blocks, 256, SCAN_SMEM_BYTES>>>(Dp);
    }

    // 4) gate + RMSNorm + split
    gatenorm_k<<<BLROWS, 512>>>(norm_w);

    // 5) out = y @ W_out   (128x128 tile — better wave balance at N=768)
    mma_gemm_k<128, 256><<<dim3(DM / 128, BLROWS / 128), 256, SMEM_BM128>>>(
        yh, yl, woh, wol, out, DM, DIN);
}

// round 11
// speedup vs baseline: 1.2086x; 1.2086x over previous
#include <cuda_runtime.h>
#include <cuda_fp16.h>
#include <cstdint>

// ---------------- problem constants ----------------
#define BB      2
#define LL      4096
#define DM      768
#define DIN     1536
#define NH      24
#define HD      64
#define DS      64
#define CONVD   1664          // DIN + 2*DS
#define DPROJ   3224          // 2*DIN + 2*DS + NH
#define BLROWS  (BB*LL)       // 8192
#define CHUNK   64
#define NCHUNK  (LL/CHUNK)    // 64
#define HG      4             // heads per scan block

// single dynamic-smem symbol for the whole TU
extern __shared__ unsigned char dynsm[];

// ---------------- scratch ----------------
__device__ float g_zx   [(size_t)BLROWS*DPROJ];
__device__ float g_xbc  [(size_t)BLROWS*CONVD];
__device__ float g_dt   [(size_t)BLROWS*NH];
__device__ float g_dA   [(size_t)BLROWS*NH];
__device__ float g_S    [(size_t)BB*NH*NCHUNK*DS*HD];
__device__ float g_hini [(size_t)BB*NH*NCHUNK*DS*HD];
__device__ float g_P    [BB*NH*NCHUNK];
__device__ float g_y    [(size_t)BLROWS*DIN];

// fp16 split operands (activations: hi+lo; weights: single rounding)
__device__ __half g_xh [(size_t)BLROWS*DM];
__device__ __half g_xl [(size_t)BLROWS*DM];
__device__ __half g_wih[(size_t)DPROJ*DM];      // W_in^T  [N][K] fp16
__device__ __half g_yh [(size_t)BLROWS*DIN];
__device__ __half g_yl [(size_t)BLROWS*DIN];
__device__ __half g_woh[(size_t)DM*DIN];        // W_out^T [N][K] fp16

// ---------------- packed f32x2 helpers ----------------
typedef unsigned long long u64t;
__device__ __forceinline__ u64t pack2(float v) {
    u64t r; asm("mov.b64 %0, {%1,%1};" : "=l"(r) : "f"(v)); return r;
}
__device__ __forceinline__ u64t fma2(u64t a, u64t b, u64t c) {
    u64t d; asm("fma.rn.f32x2 %0, %1, %2, %3;" : "=l"(d) : "l"(a), "l"(b), "l"(c)); return d;
}
__device__ __forceinline__ u64t mul2(u64t a, u64t b) {
    u64t d; asm("mul.rn.f32x2 %0, %1, %2;" : "=l"(d) : "l"(a), "l"(b)); return d;
}
__device__ __forceinline__ void unpack2(u64t v, float& lo, float& hi) {
    asm("mov.b64 {%0,%1}, %2;" : "=f"(lo), "=f"(hi) : "l"(v));
}

// ======================= split helpers =====================================
__global__ void __launch_bounds__(256) split_x_k(
    const float* __restrict__ X, __half* __restrict__ Xh,
    __half* __restrict__ Xl, int n4)
{
    int i = blockIdx.x * blockDim.x + threadIdx.x;
    if (i >= n4) return;
    float4 v = reinterpret_cast<const float4*>(X)[i];
    __half h0 = __float2half(v.x), h1 = __float2half(v.y);
    __half h2 = __float2half(v.z), h3 = __float2half(v.w);
    __half2 hh0{h0, h1}, hh1{h2, h3};
    __half2 ll0{__float2half(v.x - __half2float(h0)),
                __float2half(v.y - __half2float(h1))};
    __half2 ll1{__float2half(v.z - __half2float(h2)),
                __float2half(v.w - __half2float(h3))};
    reinterpret_cast<__half2*>(Xh)[i * 2 + 0] = hh0;
    reinterpret_cast<__half2*>(Xh)[i * 2 + 1] = hh1;
    reinterpret_cast<__half2*>(Xl)[i * 2 + 0] = ll0;
    reinterpret_cast<__half2*>(Xl)[i * 2 + 1] = ll1;
}

// W[K][N] -> T[N][K] fp16 (single rounding)
__global__ void __launch_bounds__(256) tsplit_k(
    const float* __restrict__ W, __half* __restrict__ Th, int K, int N)
{
    __shared__ float tile[32][33];
    int k0 = blockIdx.x * 32, n0 = blockIdx.y * 32;
    int tx = threadIdx.x % 32, ty = threadIdx.x / 32;
#pragma unroll
    for (int i = ty; i < 32; i += 8) {
        int k = k0 + i, n = n0 + tx;
        tile[i][tx] = (k < K && n < N) ? W[(size_t)k * N + n] : 0.f;
    }
    __syncthreads();
#pragma unroll
    for (int i = ty; i < 32; i += 8) {
        int n = n0 + i, k = k0 + tx;
        if (n < N && k < K)
            Th[(size_t)n * K + k] = __float2half(tile[tx][i]);
    }
}

// ======================= tensor-core fp16-split GEMM ========================
// C[M,N](fp32) = Ah@Bh^T + Al@Bh^T  (= A@Bh exactly in A; err = W fp16 rounding)
// Templated: BM x 128 CTA tile, NT threads, warp tile 64x32,
// 3-stage cp.async pipeline, 1 barrier per iter.
#define GSTRIDE 40
#define BPART   (128*GSTRIDE)          // B elems per stage

__device__ __forceinline__ void cp16(uint32_t s, const void* g, bool pred) {
    int sz = pred ? 16 : 0;
    asm volatile("cp.async.cg.shared.global [%0], [%1], 16, %2;\n"
                 :: "r"(s), "l"(g), "r"(sz));
}
__device__ __forceinline__ void mma_fp16(float* d, const uint32_t* a, const uint32_t* b) {
    asm volatile("mma.sync.aligned.m16n8k16.row.col.f32.f16.f16.f32 "
                 "{%0,%1,%2,%3}, {%4,%5,%6,%7}, {%8,%9}, {%0,%1,%2,%3};"
                 : "+f"(d[0]), "+f"(d[1]), "+f"(d[2]), "+f"(d[3])
                 : "r"(a[0]), "r"(a[1]), "r"(a[2]), "r"(a[3]), "r"(b[0]), "r"(b[1]));
}
__device__ __forceinline__ void ldsm4(uint32_t* r, uint32_t a) {
    asm volatile("ldmatrix.sync.aligned.m8n8.x4.shared.b16 {%0,%1,%2,%3}, [%4];"
                 : "=r"(r[0]), "=r"(r[1]), "=r"(r[2]), "=r"(r[3]) : "r"(a));
}

template <int BM, int NT>
__global__ void __launch_bounds__(NT) mma_gemm_k(
    const __half* __restrict__ Ah, const __half* __restrict__ Al,
    const __half* __restrict__ Bh,
    float* __restrict__ C, int Nn, int K)
{
    constexpr int APART = BM * GSTRIDE;                  // elems per A half
    constexpr int STAGE_BYTES = (2 * APART + BPART) * 2;
    constexpr int AROWS_PER_STEP = NT / 4;               // rows covered per load step
    constexpr int NA = BM / AROWS_PER_STEP;              // A load steps
    constexpr int NB = 128 / AROWS_PER_STEP;             // B load steps

    const int tid  = threadIdx.x;
    const int lane = tid & 31;
    const int wid  = tid >> 5;
    const int wm   = wid >> 2;           // 0..BM/64-1
    const int wn   = wid & 3;            // 0..3
    const int g    = lane >> 2;
    const int tig  = lane & 3;

    const int row0 = blockIdx.y * BM;
    const int col0 = blockIdx.x * 128;
    const int iters = K / 32;
    const int r0 = tid >> 2, s0 = tid & 3;

    // ldmatrix lane address components
    const int arow = (lane & 7) + ((lane >> 3) & 1) * 8;
    const int acol = ((lane >> 4) & 1) * 8;
    const int brow = (lane & 7) + ((lane >> 4) & 1) * 8;
    const int bcol = ((lane >> 3) & 1) * 8;

    const uint32_t smbase = (uint32_t)__cvta_generic_to_shared(dynsm);
    uint32_t aoff[4], boff[2];
#pragma unroll
    for (int mi = 0; mi < 4; mi++)
        aoff[mi] = (uint32_t)(((wm * 64 + mi * 16 + arow) * GSTRIDE + acol) * 2);
#pragma unroll
    for (int nj = 0; nj < 2; nj++)
        boff[nj] = (uint32_t)(((wn * 32 + nj * 16 + brow) * GSTRIDE + bcol) * 2);

    float acc[4][4][4];
#pragma unroll
    for (int mi = 0; mi < 4; mi++)
#pragma unroll
        for (int ni = 0; ni < 4; ni++)
#pragma unroll
            for (int q = 0; q < 4; q++) acc[mi][ni][q] = 0.f;

    auto load_tiles = [&](int buf, int it) {
        const int k0 = it * 32;
        uint32_t b = smbase + buf * STAGE_BYTES;
#pragma unroll
        for (int j = 0; j < NA; j++) {
            int r = r0 + j * AROWS_PER_STEP;
            uint32_t soff = (uint32_t)(r * GSTRIDE + s0 * 8) * 2;
            size_t ga = (size_t)(row0 + r) * K + k0 + s0 * 8;
            cp16(b + soff, Ah + ga, true);
            cp16(b + APART * 2 + soff, Al + ga, true);
        }
#pragma unroll
        for (int j = 0; j < NB; j++) {
            int r = (r0 + j * AROWS_PER_STEP) & 127;
            if (NB == 2 || r0 < 128) {
                uint32_t soff = (uint32_t)(r * GSTRIDE + s0 * 8) * 2;
                int nb = col0 + r;
                bool p = nb < Nn;
                size_t gb = (size_t)(p ? nb : 0) * K + k0 + s0 * 8;
                cp16(b + 2 * APART * 2 + soff, Bh + gb, p);
            }
        }
        asm volatile("cp.async.commit_group;\n" ::);
    };

    // prologue: fill 2 of 3 stages
    load_tiles(0, 0);
    load_tiles(1, 1);

    for (int it = 0; it < iters; it++) {
        asm volatile("cp.async.wait_group 1;\n" ::);
        __syncthreads();

        const int buf = it % 3;
        uint32_t bA  = smbase + buf * STAGE_BYTES;
        uint32_t bAl = bA + APART * 2;
        uint32_t bBh = bA + 2 * APART * 2;

#pragma unroll
        for (int kk = 0; kk < 2; kk++) {
            const uint32_t kof = kk * 32;   // 16 fp16 = 32 bytes
            uint32_t ah[4][4], al[4][4], bh[2][4];
#pragma unroll
            for (int mi = 0; mi < 4; mi++) ldsm4(ah[mi], bA + aoff[mi] + kof);
#pragma unroll
            for (int mi = 0; mi < 4; mi++) ldsm4(al[mi], bAl + aoff[mi] + kof);
#pragma unroll
            for (int nj = 0; nj < 2; nj++) ldsm4(bh[nj], bBh + boff[nj] + kof);

#pragma unroll
            for (int mi = 0; mi < 4; mi++)
#pragma unroll
                for (int ni = 0; ni < 4; ni++)
                    mma_fp16(acc[mi][ni], ah[mi], &bh[ni >> 1][(ni & 1) * 2]);
#pragma unroll
            for (int mi = 0; mi < 4; mi++)
#pragma unroll
                for (int ni = 0; ni < 4; ni++)
                    mma_fp16(acc[mi][ni], al[mi], &bh[ni >> 1][(ni & 1) * 2]);
        }

        const int nx = it + 2;
        if (nx < iters) {
            load_tiles(nx % 3, nx);
        } else {
            asm volatile("cp.async.commit_group;\n" ::);   // keep group count uniform
        }
    }

#pragma unroll
    for (int mi = 0; mi < 4; mi++) {
        int ra = row0 + wm * 64 + mi * 16 + g;
#pragma unroll
        for (int ni = 0; ni < 4; ni++) {
            int c = col0 + wn * 32 + ni * 8 + 2 * tig;
            if (c < Nn) {
                *reinterpret_cast<float2*>(&C[(size_t)ra * Nn + c]) =
                    make_float2(acc[mi][ni][0], acc[mi][ni][1]);
                *reinterpret_cast<float2*>(&C[(size_t)(ra + 8) * Nn + c]) =
                    make_float2(acc[mi][ni][2], acc[mi][ni][3]);
            }
        }
    }
}

#define SMEM_BM256 (3 * (2 * 256 * GSTRIDE + 128 * GSTRIDE) * 2)   // 153600
#define SMEM_BM128 (3 * (2 * 128 * GSTRIDE + 128 * GSTRIDE) * 2)   // 92160

// ---------------- conv: smem-tiled depthwise causal conv + silu -------------
__global__ void __launch_bounds__(256) conv_k(
    const float* __restrict__ conv_w, const float* __restrict__ conv_b)
{
    __shared__ float st[35][128];
    const int c0 = blockIdx.x * 128;
    const int b  = blockIdx.y >> 7;           // /128
    const int lg = blockIdx.y & 127;
    const int l0 = lg * 32;

    for (int i = threadIdx.x; i < 35 * 128; i += 256) {
        int r = i >> 7, cc = i & 127;
        int ls = l0 - 3 + r;
        st[r][cc] = (ls >= 0) ? g_zx[(size_t)(b * LL + ls) * DPROJ + DIN + c0 + cc] : 0.f;
    }
    __syncthreads();

    for (int i = threadIdx.x; i < 32 * 128; i += 256) {
        int r = i >> 7, cc = i & 127;
        int c = c0 + cc;
        float w0 = conv_w[c * 4 + 0], w1 = conv_w[c * 4 + 1];
        float w2 = conv_w[c * 4 + 2], w3 = conv_w[c * 4 + 3];
        float acc = conv_b[c];
        acc = fmaf(st[r + 0][cc], w0, acc);
        acc = fmaf(st[r + 1][cc], w1, acc);
        acc = fmaf(st[r + 2][cc], w2, acc);
        acc = fmaf(st[r + 3][cc], w3, acc);
        g_xbc[(size_t)(b * LL + l0 + r) * CONVD + c] = acc / (1.f + __expf(-acc));
    }
}

// ---------------- dt prep ----------------------------------------------------
__global__ void __launch_bounds__(256) dt_k(
    const float* __restrict__ dt_bias, const float* __restrict__ A_log)
{
    int i = blockIdx.x * blockDim.x + threadIdx.x;
    if (i >= BLROWS * NH) return;
    int row = i / NH, h = i % NH;
    float v = g_zx[(size_t)row * DPROJ + (DIN + CONVD) + h] + dt_bias[h];
    float sp = (v > 20.f) ? v : log1pf(expf(v));
    float Ah = -expf(A_log[h]);
    g_dt[i] = sp;
    g_dA[i] = expf(sp * Ah);
}

// ---------------- scan smem layout (floats) ----------------------------------
#define SC_B   0
#define SC_C   4096
#define SC_DA  8192
#define SC_DT  8448
#define SC_X   8704
#define SCAN_SMEM_FLOATS (8704 + HG*64*64)
#define SCAN_SMEM_BYTES  (SCAN_SMEM_FLOATS*4)    // 100352

__device__ __forceinline__ void scan_stage(float* sm, int b, int c, int hg, bool withC)
{
    const int tid = threadIdx.x;
    const int rowbase = b * LL + c * CHUNK;
    for (int i = tid; i < 64 * 16; i += 256) {
        int t = i >> 4, q = i & 15;
        const float* xr = g_xbc + (size_t)(rowbase + t) * CONVD;
        *reinterpret_cast<float4*>(sm + SC_B + t * 64 + q * 4) =
            *reinterpret_cast<const float4*>(xr + DIN + q * 4);
        if (withC)
            *reinterpret_cast<float4*>(sm + SC_C + t * 64 + q * 4) =
                *reinterpret_cast<const float4*>(xr + DIN + DS + q * 4);
    }
    for (int i = tid; i < HG * 64; i += 256) {
        int hl = i >> 6, t = i & 63;
        int row = rowbase + t;
        sm[SC_DA + i] = g_dA[(size_t)row * NH + hg * HG + hl];
        sm[SC_DT + i] = g_dt[(size_t)row * NH + hg * HG + hl];
    }
    for (int i = tid; i < HG * 64 * 16; i += 256) {
        int hl = i >> 10, rem = i & 1023, t = rem >> 4, q = rem & 15;
        const float* xr = g_xbc + (size_t)(rowbase + t) * CONVD;
        *reinterpret_cast<float4*>(sm + SC_X + hl * 4096 + t * 64 + q * 4) =
            *reinterpret_cast<const float4*>(xr + (hg * HG + hl) * HD + q * 4);
    }
}

// ---------------- scan pass 1 -----------------------------------------------
__global__ void __launch_bounds__(256) scan1_k()
{
    float* sm = reinterpret_cast<float*>(dynsm);
    const int bx = blockIdx.x;
    const int c  = bx % NCHUNK;
    const int r2 = bx / NCHUNK;
    const int b  = r2 / (NH / HG);
    const int hg = r2 % (NH / HG);

    scan_stage(sm, b, c, hg, false);
    __syncthreads();

    const int wid  = threadIdx.x >> 5;
    const int lane = threadIdx.x & 31;
    const int hl   = wid >> 1;
    const int pg   = wid & 1;
    const int p    = pg * 32 + lane;
    const int h    = hg * HG + hl;

    u64t st[32];
#pragma unroll
    for (int n = 0; n < 32; n++) st[n] = 0ull;
    float Pp = 1.f;

    const float* sxp = sm + SC_X + hl * 4096 + p;
    const float* sdA = sm + SC_DA + hl * 64;
    const float* sdt = sm + SC_DT + hl * 64;

    for (int t = 0; t < CHUNK; t++) {
        float dAv = sdA[t];
        float u = sdt[t] * sxp[t * 64];
        Pp *= dAv;
        u64t dA2 = pack2(dAv), u2 = pack2(u);
        const ulonglong2* B2 = reinterpret_cast<const ulonglong2*>(sm + SC_B + t * 64);
#pragma unroll
        for (int n4 = 0; n4 < 16; n4++) {
            ulonglong2 bb = B2[n4];
            st[2 * n4 + 0] = fma2(dA2, st[2 * n4 + 0], mul2(u2, bb.x));
            st[2 * n4 + 1] = fma2(dA2, st[2 * n4 + 1], mul2(u2, bb.y));
        }
    }

    const int bhc = (b * NH + h) * NCHUNK + c;
    float* Sp = g_S + (size_t)bhc * DS * HD;
#pragma unroll
    for (int n2 = 0; n2 < 32; n2++) {
        float lo, hi; unpack2(st[n2], lo, hi);
        Sp[(2 * n2 + 0) * HD + p] = lo;
        Sp[(2 * n2 + 1) * HD + p] = hi;
    }
    if (pg == 0 && lane == 0) g_P[bhc] = Pp;
}

// ---------------- combine ----------------------------------------------------
__global__ void __launch_bounds__(256) combine_k()
{
    const int i = blockIdx.x * blockDim.x + threadIdx.x;
    if (i >= BB * NH * DS * HD) return;
    const int pn = i % (DS * HD);
    const int bh = i / (DS * HD);
    float hp = 0.f;
    const float* P = g_P + bh * NCHUNK;
    const size_t base = (size_t)bh * NCHUNK * DS * HD + pn;
    for (int c = 0; c < NCHUNK; c++) {
        g_hini[base + (size_t)c * DS * HD] = hp;
        hp = fmaf(hp, P[c], g_S[base + (size_t)c * DS * HD]);
    }
}

// ---------------- scan pass 2 -----------------------------------------------
__global__ void __launch_bounds__(256) scan2_k(const float* __restrict__ Dp)
{
    float* sm = reinterpret_cast<float*>(dynsm);
    const int bx = blockIdx.x;
    const int c  = bx % NCHUNK;
    const int r2 = bx / NCHUNK;
    const int b  = r2 / (NH / HG);
    const int hg = r2 % (NH / HG);

    scan_stage(sm, b, c, hg, true);
    __syncthreads();

    const int wid  = threadIdx.x >> 5;
    const int lane = threadIdx.x & 31;
    const int hl   = wid >> 1;
    const int pg   = wid & 1;
    const int p    = pg * 32 + lane;
    const int h    = hg * HG + hl;
    const int bhc  = (b * NH + h) * NCHUNK + c;

    u64t st[32];
    const float* hiv = g_hini + (size_t)bhc * DS * HD;
#pragma unroll
    for (int n2 = 0; n2 < 32; n2++) {
        float lo = hiv[(2 * n2 + 0) * HD + p];
        float hi = hiv[(2 * n2 + 1) * HD + p];
        u64t v; asm("mov.b64 %0, {%1,%2};" : "=l"(v) : "f"(lo), "f"(hi));
        st[n2] = v;
    }

    const float Dh = Dp[h];
    const float* sxp = sm + SC_X + hl * 4096 + p;
    const float* sdA = sm + SC_DA + hl * 64;
    const float* sdt = sm + SC_DT + hl * 64;
    const int rowbase = b * LL + c * CHUNK;

    for (int t = 0; t < CHUNK; t++) {
        float dAv = sdA[t];
        float x = sxp[t * 64];
        float u = sdt[t] * x;
        u64t dA2 = pack2(dAv), u2 = pack2(u);
        u64t y2 = 0ull;
        const ulonglong2* B2 = reinterpret_cast<const ulonglong2*>(sm + SC_B + t * 64);
        const ulonglong2* C2 = reinterpret_cast<const ulonglong2*>(sm + SC_C + t * 64);
#pragma unroll
        for (int n4 = 0; n4 < 16; n4++) {
            ulonglong2 bb = B2[n4];
            ulonglong2 cc = C2[n4];
            st[2 * n4 + 0] = fma2(dA2, st[2 * n4 + 0], mul2(u2, bb.x));
            st[2 * n4 + 1] = fma2(dA2, st[2 * n4 + 1], mul2(u2, bb.y));
            y2 = fma2(st[2 * n4 + 0], cc.x, y2);
            y2 = fma2(st[2 * n4 + 1], cc.y, y2);
        }
        float ylo, yhi; unpack2(y2, ylo, yhi);
        g_y[(size_t)(rowbase + t) * DIN + h * HD + p] = fmaf(Dh, x, ylo + yhi);
    }
}

// ---------------- gate + RMSNorm + split to fp16 ----------------------------
__global__ void __launch_bounds__(512) gatenorm_k(const float* __restrict__ norm_w)
{
    const int row = blockIdx.x;
    const float* zrow = g_zx + (size_t)row * DPROJ;
    const float* yrow = g_y + (size_t)row * DIN;

    float gv[3];
    float ss = 0.f;
#pragma unroll
    for (int j = 0; j < 3; j++) {
        int i = threadIdx.x + j * 512;
        float z = zrow[i];
        float gg = yrow[i] * (z / (1.f + __expf(-z)));
        gv[j] = gg;
        ss = fmaf(gg, gg, ss);
    }

    __shared__ float red[16];
#pragma unroll
    for (int o = 16; o; o >>= 1) ss += __shfl_xor_sync(0xffffffffu, ss, o);
    if ((threadIdx.x & 31) == 0) red[threadIdx.x >> 5] = ss;
    __syncthreads();
    if (threadIdx.x < 16) {
        float v = red[threadIdx.x];
#pragma unroll
        for (int o = 8; o; o >>= 1) v += __shfl_xor_sync(0x0000ffffu, v, o);
        if (threadIdx.x == 0) red[0] = v;
    }
    __syncthreads();
    const float scale = rsqrtf(red[0] / (float)DIN + 1e-5f);
#pragma unroll
    for (int j = 0; j < 3; j++) {
        int i = threadIdx.x + j * 512;
        float v = gv[j] * scale * norm_w[i];
        __half h = __float2half(v);
        g_yh[(size_t)row * DIN + i] = h;
        g_yl[(size_t)row * DIN + i] = __float2half(v - __half2float(h));
    }
}

// ---------------- launch ----------------------------------------------------
extern "C" void kernel_launch(void* const* d_in, const int* in_sizes, int n_in,
                              void* d_out, int out_size)
{
    const float* x       = (const float*)d_in[0];
    const float* W_in    = (const float*)d_in[1];
    const float* conv_w  = (const float*)d_in[2];
    const float* conv_b  = (const float*)d_in[3];
    const float* dt_bias = (const float*)d_in[4];
    const float* A_log   = (const float*)d_in[5];
    const float* Dp      = (const float*)d_in[6];
    const float* norm_w  = (const float*)d_in[7];
    const float* W_out   = (const float*)d_in[8];
    float* out           = (float*)d_out;

    float* zx = nullptr;
    __half *xh, *xl, *wih, *yh, *yl, *woh;
    cudaGetSymbolAddress((void**)&zx,  g_zx);
    cudaGetSymbolAddress((void**)&xh,  g_xh);
    cudaGetSymbolAddress((void**)&xl,  g_xl);
    cudaGetSymbolAddress((void**)&wih, g_wih);
    cudaGetSymbolAddress((void**)&yh,  g_yh);
    cudaGetSymbolAddress((void**)&yl,  g_yl);
    cudaGetSymbolAddress((void**)&woh, g_woh);

    static bool attr_set = false;
    if (!attr_set) {
        cudaFuncSetAttribute(mma_gemm_k<256, 512>,
                             cudaFuncAttributeMaxDynamicSharedMemorySize, SMEM_BM256);
        cudaFuncSetAttribute(mma_gemm_k<128, 256>,
                             cudaFuncAttributeMaxDynamicSharedMemorySize, SMEM_BM128);
        cudaFuncSetAttribute(scan1_k, cudaFuncAttributeMaxDynamicSharedMemorySize,
                             SCAN_SMEM_BYTES);
        cudaFuncSetAttribute(scan2_k, cudaFuncAttributeMaxDynamicSharedMemorySize,
                             SCAN_SMEM_BYTES);
        attr_set = true;
    }

    // 0) split inputs (fp16)
    {
        int n4 = BLROWS * DM / 4;
        split_x_k<<<(n4 + 255) / 256, 256>>>(x, xh, xl, n4);
        tsplit_k<<<dim3(DM / 32, (DPROJ + 31) / 32), 256>>>(W_in, wih, DM, DPROJ);
        tsplit_k<<<dim3(DIN / 32, DM / 32), 256>>>(W_out, woh, DIN, DM);
    }

    // 1) zxbcdt = x @ W_in   (256x128 tile, 16 warps, 2-pass fp16)
    mma_gemm_k<256, 512><<<dim3((DPROJ + 127) / 128, BLROWS / 256), 512, SMEM_BM256>>>(
        xh, xl, wih, zx, DPROJ, DM);

    // 2) conv + silu ; dt prep
    conv_k<<<dim3(CONVD / 128, BB * (LL / 32)), 256>>>(conv_w, conv_b);
    dt_k<<<(BLROWS * NH + 255) / 256, 256>>>(dt_bias, A_log);

    // 3) chunked scan
    {
        int blocks = BB * (NH / HG) * NCHUNK;   // 768
        scan1_k<<<blocks, 256, SCAN_SMEM_BYTES>>>();
        int nstates = BB * NH * DS * HD;
        combine_k<<<(nstates + 255) / 256, 256>>>();
        scan2_k<<<blocks, 256, SCAN_SMEM_BYTES>>>(Dp);
    }

    // 4) gate + RMSNorm + split
    gatenorm_k<<<BLROWS, 512>>>(norm_w);

    // 5) out = y @ W_out   (128x128 tile, 2-pass fp16)
    mma_gemm_k<128, 256><<<dim3(DM / 128, BLROWS / 128), 256, SMEM_BM128>>>(
        yh, yl, woh, out, DM, DIN);
}

// round 13
// speedup vs baseline: 1.5236x; 1.2607x over previous
#include <cuda_runtime.h>
#include <cuda_fp16.h>
#include <cstdint>

// ---------------- problem constants ----------------
#define BB      2
#define LL      4096
#define DM      768
#define DIN     1536
#define NH      24
#define HD      64
#define DS      64
#define CONVD   1664          // DIN + 2*DS
#define DPROJ   3224          // 2*DIN + 2*DS + NH
#define BLROWS  (BB*LL)       // 8192
#define CHUNK   64
#define NCHUNK  (LL/CHUNK)    // 64
#define HG      4             // heads per scan block

// single dynamic-smem symbol for the whole TU
extern __shared__ unsigned char dynsm[];

// ---------------- scratch ----------------
__device__ float g_zx   [(size_t)BLROWS*DPROJ];
__device__ float g_xbc  [(size_t)BLROWS*CONVD];
__device__ float g_dt   [(size_t)BLROWS*NH];
__device__ float g_dA   [(size_t)BLROWS*NH];
__device__ float g_S    [(size_t)BB*NH*NCHUNK*DS*HD];
__device__ float g_hini [(size_t)BB*NH*NCHUNK*DS*HD];
__device__ float g_P    [BB*NH*NCHUNK];
__device__ float g_y    [(size_t)BLROWS*DIN];

// fp16 operands (single rounding for both activations and weights)
__device__ __half g_xh [(size_t)BLROWS*DM];
__device__ __half g_wih[(size_t)DPROJ*DM];      // W_in^T  [N][K] fp16
__device__ __half g_yh [(size_t)BLROWS*DIN];
__device__ __half g_woh[(size_t)DM*DIN];        // W_out^T [N][K] fp16

// ---------------- packed f32x2 helpers ----------------
typedef unsigned long long u64t;
__device__ __forceinline__ u64t pack2(float v) {
    u64t r; asm("mov.b64 %0, {%1,%1};" : "=l"(r) : "f"(v)); return r;
}
__device__ __forceinline__ u64t fma2(u64t a, u64t b, u64t c) {
    u64t d; asm("fma.rn.f32x2 %0, %1, %2, %3;" : "=l"(d) : "l"(a), "l"(b), "l"(c)); return d;
}
__device__ __forceinline__ u64t mul2(u64t a, u64t b) {
    u64t d; asm("mul.rn.f32x2 %0, %1, %2;" : "=l"(d) : "l"(a), "l"(b)); return d;
}
__device__ __forceinline__ void unpack2(u64t v, float& lo, float& hi) {
    asm("mov.b64 {%0,%1}, %2;" : "=f"(lo), "=f"(hi) : "l"(v));
}

// ======================= convert helpers ===================================
__global__ void __launch_bounds__(256) split_x_k(
    const float* __restrict__ X, __half* __restrict__ Xh, int n4)
{
    int i = blockIdx.x * blockDim.x + threadIdx.x;
    if (i >= n4) return;
    float4 v = reinterpret_cast<const float4*>(X)[i];
    __half2 hh0{__float2half(v.x), __float2half(v.y)};
    __half2 hh1{__float2half(v.z), __float2half(v.w)};
    reinterpret_cast<__half2*>(Xh)[i * 2 + 0] = hh0;
    reinterpret_cast<__half2*>(Xh)[i * 2 + 1] = hh1;
}

// W[K][N] -> T[N][K] fp16 (single rounding)
__global__ void __launch_bounds__(256) tsplit_k(
    const float* __restrict__ W, __half* __restrict__ Th, int K, int N)
{
    __shared__ float tile[32][33];
    int k0 = blockIdx.x * 32, n0 = blockIdx.y * 32;
    int tx = threadIdx.x % 32, ty = threadIdx.x / 32;
#pragma unroll
    for (int i = ty; i < 32; i += 8) {
        int k = k0 + i, n = n0 + tx;
        tile[i][tx] = (k < K && n < N) ? W[(size_t)k * N + n] : 0.f;
    }
    __syncthreads();
#pragma unroll
    for (int i = ty; i < 32; i += 8) {
        int n = n0 + i, k = k0 + tx;
        if (n < N && k < K)
            Th[(size_t)n * K + k] = __float2half(tile[tx][i]);
    }
}

// ======================= tensor-core fp16 GEMM =============================
// C[M,N](fp32) = Ah@Bh^T ; A[M][K] fp16, B stored [N][K] fp16.
// Templated: BM x 128 CTA tile, NT threads, warp tile 64x32,
// 3-stage cp.async pipeline, 1 barrier per iter.
#define GSTRIDE 40
#define BPART   (128*GSTRIDE)          // B elems per stage

__device__ __forceinline__ void cp16(uint32_t s, const void* g, bool pred) {
    int sz = pred ? 16 : 0;
    asm volatile("cp.async.cg.shared.global [%0], [%1], 16, %2;\n"
                 :: "r"(s), "l"(g), "r"(sz));
}
__device__ __forceinline__ void mma_fp16(float* d, const uint32_t* a, const uint32_t* b) {
    asm volatile("mma.sync.aligned.m16n8k16.row.col.f32.f16.f16.f32 "
                 "{%0,%1,%2,%3}, {%4,%5,%6,%7}, {%8,%9}, {%0,%1,%2,%3};"
                 : "+f"(d[0]), "+f"(d[1]), "+f"(d[2]), "+f"(d[3])
                 : "r"(a[0]), "r"(a[1]), "r"(a[2]), "r"(a[3]), "r"(b[0]), "r"(b[1]));
}
__device__ __forceinline__ void ldsm4(uint32_t* r, uint32_t a) {
    asm volatile("ldmatrix.sync.aligned.m8n8.x4.shared.b16 {%0,%1,%2,%3}, [%4];"
                 : "=r"(r[0]), "=r"(r[1]), "=r"(r[2]), "=r"(r[3]) : "r"(a));
}

template <int BM, int NT>
__global__ void __launch_bounds__(NT) mma_gemm_k(
    const __half* __restrict__ Ah, const __half* __restrict__ Bh,
    float* __restrict__ C, int Nn, int K)
{
    constexpr int APART = BM * GSTRIDE;                  // A elems per stage
    constexpr int STAGE_BYTES = (APART + BPART) * 2;
    constexpr int AROWS_PER_STEP = NT / 4;               // rows covered per load step
    constexpr int NA = BM / AROWS_PER_STEP;              // A load steps
    constexpr int NB = 128 / AROWS_PER_STEP;             // B load steps

    const int tid  = threadIdx.x;
    const int lane = tid & 31;
    const int wid  = tid >> 5;
    const int wm   = wid >> 2;           // 0..BM/64-1
    const int wn   = wid & 3;            // 0..3
    const int g    = lane >> 2;
    const int tig  = lane & 3;

    const int row0 = blockIdx.y * BM;
    const int col0 = blockIdx.x * 128;
    const int iters = K / 32;
    const int r0 = tid >> 2, s0 = tid & 3;

    // ldmatrix lane address components
    const int arow = (lane & 7) + ((lane >> 3) & 1) * 8;
    const int acol = ((lane >> 4) & 1) * 8;
    const int brow = (lane & 7) + ((lane >> 4) & 1) * 8;
    const int bcol = ((lane >> 3) & 1) * 8;

    const uint32_t smbase = (uint32_t)__cvta_generic_to_shared(dynsm);
    uint32_t aoff[4], boff[2];
#pragma unroll
    for (int mi = 0; mi < 4; mi++)
        aoff[mi] = (uint32_t)(((wm * 64 + mi * 16 + arow) * GSTRIDE + acol) * 2);
#pragma unroll
    for (int nj = 0; nj < 2; nj++)
        boff[nj] = (uint32_t)(((wn * 32 + nj * 16 + brow) * GSTRIDE + bcol) * 2);

    float acc[4][4][4];
#pragma unroll
    for (int mi = 0; mi < 4; mi++)
#pragma unroll
        for (int ni = 0; ni < 4; ni++)
#pragma unroll
            for (int q = 0; q < 4; q++) acc[mi][ni][q] = 0.f;

    auto load_tiles = [&](int buf, int it) {
        const int k0 = it * 32;
        uint32_t b = smbase + buf * STAGE_BYTES;
#pragma unroll
        for (int j = 0; j < NA; j++) {
            int r = r0 + j * AROWS_PER_STEP;
            uint32_t soff = (uint32_t)(r * GSTRIDE + s0 * 8) * 2;
            size_t ga = (size_t)(row0 + r) * K + k0 + s0 * 8;
            cp16(b + soff, Ah + ga, true);
        }
#pragma unroll
        for (int j = 0; j < NB; j++) {
            int r = (r0 + j * AROWS_PER_STEP) & 127;
            if (NB == 2 || r0 < 128) {
                uint32_t soff = (uint32_t)(r * GSTRIDE + s0 * 8) * 2;
                int nb = col0 + r;
                bool p = nb < Nn;
                size_t gb = (size_t)(p ? nb : 0) * K + k0 + s0 * 8;
                cp16(b + APART * 2 + soff, Bh + gb, p);
            }
        }
        asm volatile("cp.async.commit_group;\n" ::);
    };

    // prologue: fill 2 of 3 stages
    load_tiles(0, 0);
    load_tiles(1, 1);

    for (int it = 0; it < iters; it++) {
        asm volatile("cp.async.wait_group 1;\n" ::);
        __syncthreads();

        const int buf = it % 3;
        uint32_t bA  = smbase + buf * STAGE_BYTES;
        uint32_t bBh = bA + APART * 2;

#pragma unroll
        for (int kk = 0; kk < 2; kk++) {
            const uint32_t kof = kk * 32;   // 16 fp16 = 32 bytes
            uint32_t ah[4][4], bh[2][4];
#pragma unroll
            for (int mi = 0; mi < 4; mi++) ldsm4(ah[mi], bA + aoff[mi] + kof);
#pragma unroll
            for (int nj = 0; nj < 2; nj++) ldsm4(bh[nj], bBh + boff[nj] + kof);

#pragma unroll
            for (int mi = 0; mi < 4; mi++)
#pragma unroll
                for (int ni = 0; ni < 4; ni++)
                    mma_fp16(acc[mi][ni], ah[mi], &bh[ni >> 1][(ni & 1) * 2]);
        }

        const int nx = it + 2;
        if (nx < iters) {
            load_tiles(nx % 3, nx);
        } else {
            asm volatile("cp.async.commit_group;\n" ::);   // keep group count uniform
        }
    }

#pragma unroll
    for (int mi = 0; mi < 4; mi++) {
        int ra = row0 + wm * 64 + mi * 16 + g;
#pragma unroll
        for (int ni = 0; ni < 4; ni++) {
            int c = col0 + wn * 32 + ni * 8 + 2 * tig;
            if (c < Nn) {
                *reinterpret_cast<float2*>(&C[(size_t)ra * Nn + c]) =
                    make_float2(acc[mi][ni][0], acc[mi][ni][1]);
                *reinterpret_cast<float2*>(&C[(size_t)(ra + 8) * Nn + c]) =
                    make_float2(acc[mi][ni][2], acc[mi][ni][3]);
            }
        }
    }
}

#define SMEM_BM256 (3 * (256 * GSTRIDE + 128 * GSTRIDE) * 2)   // 92160
#define SMEM_BM128 (3 * (128 * GSTRIDE + 128 * GSTRIDE) * 2)   // 61440

// ---------------- conv: smem-tiled depthwise causal conv + silu -------------
__global__ void __launch_bounds__(256) conv_k(
    const float* __restrict__ conv_w, const float* __restrict__ conv_b)
{
    __shared__ float st[35][128];
    const int c0 = blockIdx.x * 128;
    const int b  = blockIdx.y >> 7;           // /128
    const int lg = blockIdx.y & 127;
    const int l0 = lg * 32;

    for (int i = threadIdx.x; i < 35 * 128; i += 256) {
        int r = i >> 7, cc = i & 127;
        int ls = l0 - 3 + r;
        st[r][cc] = (ls >= 0) ? g_zx[(size_t)(b * LL + ls) * DPROJ + DIN + c0 + cc] : 0.f;
    }
    __syncthreads();

    for (int i = threadIdx.x; i < 32 * 128; i += 256) {
        int r = i >> 7, cc = i & 127;
        int c = c0 + cc;
        float w0 = conv_w[c * 4 + 0], w1 = conv_w[c * 4 + 1];
        float w2 = conv_w[c * 4 + 2], w3 = conv_w[c * 4 + 3];
        float acc = conv_b[c];
        acc = fmaf(st[r + 0][cc], w0, acc);
        acc = fmaf(st[r + 1][cc], w1, acc);
        acc = fmaf(st[r + 2][cc], w2, acc);
        acc = fmaf(st[r + 3][cc], w3, acc);
        g_xbc[(size_t)(b * LL + l0 + r) * CONVD + c] = acc / (1.f + __expf(-acc));
    }
}

// ---------------- dt prep ----------------------------------------------------
__global__ void __launch_bounds__(256) dt_k(
    const float* __restrict__ dt_bias, const float* __restrict__ A_log)
{
    int i = blockIdx.x * blockDim.x + threadIdx.x;
    if (i >= BLROWS * NH) return;
    int row = i / NH, h = i % NH;
    float v = g_zx[(size_t)row * DPROJ + (DIN + CONVD) + h] + dt_bias[h];
    float sp = (v > 20.f) ? v : log1pf(expf(v));
    float Ah = -expf(A_log[h]);
    g_dt[i] = sp;
    g_dA[i] = expf(sp * Ah);
}

// ---------------- scan smem layout (floats) ----------------------------------
#define SC_B   0
#define SC_C   4096
#define SC_DA  8192
#define SC_DT  8448
#define SC_X   8704
#define SCAN_SMEM_FLOATS (8704 + HG*64*64)
#define SCAN_SMEM_BYTES  (SCAN_SMEM_FLOATS*4)    // 100352

__device__ __forceinline__ void scan_stage(float* sm, int b, int c, int hg, bool withC)
{
    const int tid = threadIdx.x;
    const int rowbase = b * LL + c * CHUNK;
    for (int i = tid; i < 64 * 16; i += 256) {
        int t = i >> 4, q = i & 15;
        const float* xr = g_xbc + (size_t)(rowbase + t) * CONVD;
        *reinterpret_cast<float4*>(sm + SC_B + t * 64 + q * 4) =
            *reinterpret_cast<const float4*>(xr + DIN + q * 4);
        if (withC)
            *reinterpret_cast<float4*>(sm + SC_C + t * 64 + q * 4) =
                *reinterpret_cast<const float4*>(xr + DIN + DS + q * 4);
    }
    for (int i = tid; i < HG * 64; i += 256) {
        int hl = i >> 6, t = i & 63;
        int row = rowbase + t;
        sm[SC_DA + i] = g_dA[(size_t)row * NH + hg * HG + hl];
        sm[SC_DT + i] = g_dt[(size_t)row * NH + hg * HG + hl];
    }
    for (int i = tid; i < HG * 64 * 16; i += 256) {
        int hl = i >> 10, rem = i & 1023, t = rem >> 4, q = rem & 15;
        const float* xr = g_xbc + (size_t)(rowbase + t) * CONVD;
        *reinterpret_cast<float4*>(sm + SC_X + hl * 4096 + t * 64 + q * 4) =
            *reinterpret_cast<const float4*>(xr + (hg * HG + hl) * HD + q * 4);
    }
}

// ---------------- scan pass 1 -----------------------------------------------
__global__ void __launch_bounds__(256) scan1_k()
{
    float* sm = reinterpret_cast<float*>(dynsm);
    const int bx = blockIdx.x;
    const int c  = bx % NCHUNK;
    const int r2 = bx / NCHUNK;
    const int b  = r2 / (NH / HG);
    const int hg = r2 % (NH / HG);

    scan_stage(sm, b, c, hg, false);
    __syncthreads();

    const int wid  = threadIdx.x >> 5;
    const int lane = threadIdx.x & 31;
    const int hl   = wid >> 1;
    const int pg   = wid & 1;
    const int p    = pg * 32 + lane;
    const int h    = hg * HG + hl;

    u64t st[32];
#pragma unroll
    for (int n = 0; n < 32; n++) st[n] = 0ull;
    float Pp = 1.f;

    const float* sxp = sm + SC_X + hl * 4096 + p;
    const float* sdA = sm + SC_DA + hl * 64;
    const float* sdt = sm + SC_DT + hl * 64;

    for (int t = 0; t < CHUNK; t++) {
        float dAv = sdA[t];
        float u = sdt[t] * sxp[t * 64];
        Pp *= dAv;
        u64t dA2 = pack2(dAv), u2 = pack2(u);
        const ulonglong2* B2 = reinterpret_cast<const ulonglong2*>(sm + SC_B + t * 64);
#pragma unroll
        for (int n4 = 0; n4 < 16; n4++) {
            ulonglong2 bb = B2[n4];
            st[2 * n4 + 0] = fma2(dA2, st[2 * n4 + 0], mul2(u2, bb.x));
            st[2 * n4 + 1] = fma2(dA2, st[2 * n4 + 1], mul2(u2, bb.y));
        }
    }

    const int bhc = (b * NH + h) * NCHUNK + c;
    float* Sp = g_S + (size_t)bhc * DS * HD;
#pragma unroll
    for (int n2 = 0; n2 < 32; n2++) {
        float lo, hi; unpack2(st[n2], lo, hi);
        Sp[(2 * n2 + 0) * HD + p] = lo;
        Sp[(2 * n2 + 1) * HD + p] = hi;
    }
    if (pg == 0 && lane == 0) g_P[bhc] = Pp;
}

// ---------------- combine ----------------------------------------------------
__global__ void __launch_bounds__(256) combine_k()
{
    const int i = blockIdx.x * blockDim.x + threadIdx.x;
    if (i >= BB * NH * DS * HD) return;
    const int pn = i % (DS * HD);
    const int bh = i / (DS * HD);
    float hp = 0.f;
    const float* P = g_P + bh * NCHUNK;
    const size_t base = (size_t)bh * NCHUNK * DS * HD + pn;
    for (int c = 0; c < NCHUNK; c++) {
        g_hini[base + (size_t)c * DS * HD] = hp;
        hp = fmaf(hp, P[c], g_S[base + (size_t)c * DS * HD]);
    }
}

// ---------------- scan pass 2 -----------------------------------------------
__global__ void __launch_bounds__(256) scan2_k(const float* __restrict__ Dp)
{
    float* sm = reinterpret_cast<float*>(dynsm);
    const int bx = blockIdx.x;
    const int c  = bx % NCHUNK;
    const int r2 = bx / NCHUNK;
    const int b  = r2 / (NH / HG);
    const int hg = r2 % (NH / HG);

    scan_stage(sm, b, c, hg, true);
    __syncthreads();

    const int wid  = threadIdx.x >> 5;
    const int lane = threadIdx.x & 31;
    const int hl   = wid >> 1;
    const int pg   = wid & 1;
    const int p    = pg * 32 + lane;
    const int h    = hg * HG + hl;
    const int bhc  = (b * NH + h) * NCHUNK + c;

    u64t st[32];
    const float* hiv = g_hini + (size_t)bhc * DS * HD;
#pragma unroll
    for (int n2 = 0; n2 < 32; n2++) {
        float lo = hiv[(2 * n2 + 0) * HD + p];
        float hi = hiv[(2 * n2 + 1) * HD + p];
        u64t v; asm("mov.b64 %0, {%1,%2};" : "=l"(v) : "f"(lo), "f"(hi));
        st[n2] = v;
    }

    const float Dh = Dp[h];
    const float* sxp = sm + SC_X + hl * 4096 + p;
    const float* sdA = sm + SC_DA + hl * 64;
    const float* sdt = sm + SC_DT + hl * 64;
    const int rowbase = b * LL + c * CHUNK;

    for (int t = 0; t < CHUNK; t++) {
        float dAv = sdA[t];
        float x = sxp[t * 64];
        float u = sdt[t] * x;
        u64t dA2 = pack2(dAv), u2 = pack2(u);
        u64t y2 = 0ull;
        const ulonglong2* B2 = reinterpret_cast<const ulonglong2*>(sm + SC_B + t * 64);
        const ulonglong2* C2 = reinterpret_cast<const ulonglong2*>(sm + SC_C + t * 64);
#pragma unroll
        for (int n4 = 0; n4 < 16; n4++) {
            ulonglong2 bb = B2[n4];
            ulonglong2 cc = C2[n4];
            st[2 * n4 + 0] = fma2(dA2, st[2 * n4 + 0], mul2(u2, bb.x));
            st[2 * n4 + 1] = fma2(dA2, st[2 * n4 + 1], mul2(u2, bb.y));
            y2 = fma2(st[2 * n4 + 0], cc.x, y2);
            y2 = fma2(st[2 * n4 + 1], cc.y, y2);
        }
        float ylo, yhi; unpack2(y2, ylo, yhi);
        g_y[(size_t)(rowbase + t) * DIN + h * HD + p] = fmaf(Dh, x, ylo + yhi);
    }
}

// ---------------- gate + RMSNorm + convert to fp16 --------------------------
__global__ void __launch_bounds__(512) gatenorm_k(const float* __restrict__ norm_w)
{
    const int row = blockIdx.x;
    const float* zrow = g_zx + (size_t)row * DPROJ;
    const float* yrow = g_y + (size_t)row * DIN;

    float gv[3];
    float ss = 0.f;
#pragma unroll
    for (int j = 0; j < 3; j++) {
        int i = threadIdx.x + j * 512;
        float z = zrow[i];
        float gg = yrow[i] * (z / (1.f + __expf(-z)));
        gv[j] = gg;
        ss = fmaf(gg, gg, ss);
    }

    __shared__ float red[16];
#pragma unroll
    for (int o = 16; o; o >>= 1) ss += __shfl_xor_sync(0xffffffffu, ss, o);
    if ((threadIdx.x & 31) == 0) red[threadIdx.x >> 5] = ss;
    __syncthreads();
    if (threadIdx.x < 16) {
        float v = red[threadIdx.x];
#pragma unroll
        for (int o = 8; o; o >>= 1) v += __shfl_xor_sync(0x0000ffffu, v, o);
        if (threadIdx.x == 0) red[0] = v;
    }
    __syncthreads();
    const float scale = rsqrtf(red[0] / (float)DIN + 1e-5f);
#pragma unroll
    for (int j = 0; j < 3; j++) {
        int i = threadIdx.x + j * 512;
        float v = gv[j] * scale * norm_w[i];
        g_yh[(size_t)row * DIN + i] = __float2half(v);
    }
}

// ---------------- launch ----------------------------------------------------
extern "C" void kernel_launch(void* const* d_in, const int* in_sizes, int n_in,
                              void* d_out, int out_size)
{
    const float* x       = (const float*)d_in[0];
    const float* W_in    = (const float*)d_in[1];
    const float* conv_w  = (const float*)d_in[2];
    const float* conv_b  = (const float*)d_in[3];
    const float* dt_bias = (const float*)d_in[4];
    const float* A_log   = (const float*)d_in[5];
    const float* Dp      = (const float*)d_in[6];
    const float* norm_w  = (const float*)d_in[7];
    const float* W_out   = (const float*)d_in[8];
    float* out           = (float*)d_out;

    float* zx = nullptr;
    __half *xh, *wih, *yh, *woh;
    cudaGetSymbolAddress((void**)&zx,  g_zx);
    cudaGetSymbolAddress((void**)&xh,  g_xh);
    cudaGetSymbolAddress((void**)&wih, g_wih);
    cudaGetSymbolAddress((void**)&yh,  g_yh);
    cudaGetSymbolAddress((void**)&woh, g_woh);

    static bool attr_set = false;
    if (!attr_set) {
        cudaFuncSetAttribute(mma_gemm_k<256, 512>,
                             cudaFuncAttributeMaxDynamicSharedMemorySize, SMEM_BM256);
        cudaFuncSetAttribute(mma_gemm_k<128, 256>,
                             cudaFuncAttributeMaxDynamicSharedMemorySize, SMEM_BM128);
        cudaFuncSetAttribute(scan1_k, cudaFuncAttributeMaxDynamicSharedMemorySize,
                             SCAN_SMEM_BYTES);
        cudaFuncSetAttribute(scan2_k, cudaFuncAttributeMaxDynamicSharedMemorySize,
                             SCAN_SMEM_BYTES);
        attr_set = true;
    }

    // 0) convert inputs to fp16
    {
        int n4 = BLROWS * DM / 4;
        split_x_k<<<(n4 + 255) / 256, 256>>>(x, xh, n4);
        tsplit_k<<<dim3(DM / 32, (DPROJ + 31) / 32), 256>>>(W_in, wih, DM, DPROJ);
        tsplit_k<<<dim3(DIN / 32, DM / 32), 256>>>(W_out, woh, DIN, DM);
    }

    // 1) zxbcdt = x @ W_in   (256x128 tile, 16 warps, single-pass fp16)
    mma_gemm_k<256, 512><<<dim3((DPROJ + 127) / 128, BLROWS / 256), 512, SMEM_BM256>>>(
        xh, wih, zx, DPROJ, DM);

    // 2) conv + silu ; dt prep
    conv_k<<<dim3(CONVD / 128, BB * (LL / 32)), 256>>>(conv_w, conv_b);
    dt_k<<<(BLROWS * NH + 255) / 256, 256>>>(dt_bias, A_log);

    // 3) chunked scan
    {
        int blocks = BB * (NH / HG) * NCHUNK;   // 768
        scan1_k<<<blocks, 256, SCAN_SMEM_BYTES>>>();
        int nstates = BB * NH * DS * HD;
        combine_k<<<(nstates + 255) / 256, 256>>>();
        scan2_k<<<blocks, 256, SCAN_SMEM_BYTES>>>(Dp);
    }

    // 4) gate + RMSNorm + fp16 convert
    gatenorm_k<<<BLROWS, 512>>>(norm_w);

    // 5) out = y @ W_out   (128x128 tile, single-pass fp16)
    mma_gemm_k<128, 256><<<dim3(DM / 128, BLROWS / 128), 256, SMEM_BM128>>>(
        yh, woh, out, DM, DIN);
}